// round 12
// baseline (speedup 1.0000x reference)
#include <cuda_runtime.h>
#include <math_constants.h>

// CropProposals: 3D ROI 2x2x2 adaptive max-pool.
// fm:      (4, 64, 24, 24, 24) f32   -> d_in[0]
// corners: (4, 64, 2, 3)       f32   -> d_in[1]
// out:     (4, 64, 64, 2, 2, 2) f32
//
// 2-D lane mapping: W = z-union width, lane -> (hrel = lane/W, zrel = lane%W);
// one LDG covers R = 32/W h-rows. Per axis both bins have EQUAL length
// m2=(n+1)/2 starting at lo and lo+n/2 (middle slice shared, max-idempotent).
// NO predication: out-of-range lanes/steps are CLAMPED onto in-bin duplicate
// voxels (idempotent under max). 2 d-slices processed per iteration -> 8
// independent LDG streams per step, address math amortized 8 ways.
// 2 warps per (b,p,c) split d by parity; block = 8 warps = 4 channels x
// 2 halves sharing one (b,p). z-binning via redux.sync on monotone keys.

#define NEGINF (-CUDART_INF_F)
#define KEY_NEGINF 0x007FFFFFu   // f2key(-inf)

__device__ __forceinline__ unsigned f2key(float f) {
    int i = __float_as_int(f);
    return (unsigned)(i ^ ((i >> 31) | 0x80000000));
}
__device__ __forceinline__ float key2f(unsigned u) {
    int i = (int)(u ^ ((~u >> 31) ? 0xFFFFFFFFu : 0x80000000u));
    return __int_as_float(i);
}

__global__ __launch_bounds__(256) void crop_proposals_kernel(
    const float* __restrict__ fm,
    const float* __restrict__ corners,
    float* __restrict__ out)
{
    __shared__ unsigned skey[8][8];

    const int wid   = threadIdx.x >> 5;   // 0..7
    const int lane  = threadIdx.x & 31;
    const int cpair = wid >> 1;           // 0..3 : channel within block
    const int half  = wid & 1;            // 0/1  : d-parity split

    const int bp = blockIdx.x >> 4;       // b*64 + p
    const int cg = blockIdx.x & 15;       // channel group
    const int b  = bp >> 6;
    const int c  = cg * 4 + cpair;

    // ---- bin computation (matches JAX _pool_masks exactly, fp32) ----
    const float* cor = corners + bp * 6;
    int blo[3], nn[3];
#pragma unroll
    for (int a = 0; a < 3; a++) {
        float ll = __ldg(cor + a)     * 0.25f;
        float ur = __ldg(cor + 3 + a) * 0.25f;
        ll = fminf(fmaxf(ll, 0.0f), 21.0f);
        ur = (ur - ll >= 2.0f) ? ur : (ll + 2.0f);
        ur = fminf(fmaxf(ur, 2.0f), 23.0f);
        int lo = (int)floorf(ll);
        blo[a] = lo;
        nn[a]  = (int)floorf(ur) - lo;   // n in [2, 23]
    }
    // equal-length bins: [lo, lo+m2) and [lo+n/2, lo+n/2+m2), m2 = (n+1)/2
    const int d0   = blo[0], md2 = (nn[0] + 1) >> 1, ddel = (nn[0] >> 1) * 576;
    const int h0   = blo[1], mh2 = (nn[1] + 1) >> 1, hseg = (nn[1] >> 1) * 24;
    const int zlo  = blo[2], mz2 = (nn[2] + 1) >> 1, zhalf = nn[2] >> 1;

    // ---- 2-D lane mapping over (h, z); no validity mask needed: clamped
    //      lanes land on in-bin duplicate voxels (idempotent under max) ----
    const int W    = nn[2];              // z-union width (2..23)
    const int R    = 32 / W;             // h-rows per load step (1..16)
    const int hrel = lane / W;
    const int zrel = lane - hrel * W;

    const float* base = fm + ((size_t)(b * 64 + c)) * 13824 + (zlo + zrel);

    float a00 = NEGINF, a01 = NEGINF, a10 = NEGINF, a11 = NEGINF;

    // ---- main loop: warp owns i = half, half+2, ...; 2 owned d per iter ----
    for (int i = half; i < md2; i += 4) {
        const int i2 = min(i + 2, md2 - 1);          // in-bin duplicate if past end
        const float* pA  = base + (d0 + i)  * 576;   // kx0, d #1
        const float* pA2 = base + (d0 + i2) * 576;   // kx0, d #2
        const float* pC  = pA  + ddel;               // kx1, d #1
        const float* pC2 = pA2 + ddel;               // kx1, d #2
        for (int idx0 = 0; idx0 < mh2; idx0 += R) {
            const int ro = (h0 + min(idx0 + hrel, mh2 - 1)) * 24;
            const float vA0 = __ldg(pA  + ro), vA1 = __ldg(pA  + ro + hseg);
            const float vC0 = __ldg(pC  + ro), vC1 = __ldg(pC  + ro + hseg);
            const float wA0 = __ldg(pA2 + ro), wA1 = __ldg(pA2 + ro + hseg);
            const float wC0 = __ldg(pC2 + ro), wC1 = __ldg(pC2 + ro + hseg);
            a00 = fmaxf(a00, fmaxf(vA0, wA0));
            a01 = fmaxf(a01, fmaxf(vA1, wA1));
            a10 = fmaxf(a10, fmaxf(vC0, wC0));
            a11 = fmaxf(a11, fmaxf(vC1, wC1));
        }
    }

    // ---- per-warp z-bin reductions via redux.sync on monotone keys ----
    const unsigned k00 = f2key(a00), k01 = f2key(a01);
    const unsigned k10 = f2key(a10), k11 = f2key(a11);

#pragma unroll
    for (int kz = 0; kz < 2; kz++) {
        const bool inz = (unsigned)(zrel - (kz ? zhalf : 0)) < (unsigned)mz2;
        unsigned m00 = __reduce_max_sync(0xFFFFFFFFu, inz ? k00 : KEY_NEGINF);
        unsigned m01 = __reduce_max_sync(0xFFFFFFFFu, inz ? k01 : KEY_NEGINF);
        unsigned m10 = __reduce_max_sync(0xFFFFFFFFu, inz ? k10 : KEY_NEGINF);
        unsigned m11 = __reduce_max_sync(0xFFFFFFFFu, inz ? k11 : KEY_NEGINF);
        if (lane == 0) {
            skey[wid][kz + 0] = m00;   // slot = kx*4 + ky*2 + kz
            skey[wid][kz + 2] = m01;
            skey[wid][kz + 4] = m10;
            skey[wid][kz + 6] = m11;
        }
    }
    __syncthreads();

    // ---- combine halves + write: warp 0, one lane per output value ----
    if (wid == 0) {
        const int ocp = lane >> 3;     // channel pair 0..3
        const int k   = lane & 7;      // output slot kx*4+ky*2+kz
        unsigned v = max(skey[ocp * 2 + 0][k], skey[ocp * 2 + 1][k]);
        const int oc = cg * 4 + ocp;
        out[(((size_t)bp * 64 + oc) << 3) + k] = key2f(v);
    }
}

extern "C" void kernel_launch(void* const* d_in, const int* in_sizes, int n_in,
                              void* d_out, int out_size)
{
    const float* fm      = (const float*)d_in[0];
    const float* corners = (const float*)d_in[1];
    float* out           = (float*)d_out;

    // 256 (b,p) x 16 channel-groups = 4096 blocks, 8 warps each
    crop_proposals_kernel<<<4096, 256>>>(fm, corners, out);
}

// round 13
// speedup vs baseline: 1.1102x; 1.1102x over previous
#include <cuda_runtime.h>
#include <math_constants.h>

// CropProposals: 3D ROI 2x2x2 adaptive max-pool.
// fm:      (4, 64, 24, 24, 24) f32   -> d_in[0]
// corners: (4, 64, 2, 3)       f32   -> d_in[1]
// out:     (4, 64, 64, 2, 2, 2) f32
//
// 2-D lane mapping: W = z-union width, lane -> (hrel = lane/W, zrel = lane%W);
// one LDG covers R = 32/W h-rows. Per axis both bins have EQUAL length
// m2=(n+1)/2 starting at lo and lo+n/2 (middle slice shared, max-idempotent).
// NO inner-loop predication: out-of-range lanes are CLAMPED onto the last
// in-bin h-row (a duplicate of a voxel a valid lane covers; idempotent under
// max). One d-slice per iteration (R11's d-pairing regressed: duplicate d
// loads). 2 warps per (b,p,c) split d by parity; block = 8 warps = 4 channels
// x 2 halves sharing one (b,p). z-binning via redux.sync on monotone keys.

#define NEGINF (-CUDART_INF_F)
#define KEY_NEGINF 0x007FFFFFu   // f2key(-inf)

__device__ __forceinline__ unsigned f2key(float f) {
    int i = __float_as_int(f);
    return (unsigned)(i ^ ((i >> 31) | 0x80000000));
}
__device__ __forceinline__ float key2f(unsigned u) {
    int i = (int)(u ^ ((~u >> 31) ? 0xFFFFFFFFu : 0x80000000u));
    return __int_as_float(i);
}

__global__ __launch_bounds__(256) void crop_proposals_kernel(
    const float* __restrict__ fm,
    const float* __restrict__ corners,
    float* __restrict__ out)
{
    __shared__ unsigned skey[8][8];

    const int wid   = threadIdx.x >> 5;   // 0..7
    const int lane  = threadIdx.x & 31;
    const int cpair = wid >> 1;           // 0..3 : channel within block
    const int half  = wid & 1;            // 0/1  : d-parity split

    const int bp = blockIdx.x >> 4;       // b*64 + p
    const int cg = blockIdx.x & 15;       // channel group
    const int b  = bp >> 6;
    const int c  = cg * 4 + cpair;

    // ---- bin computation (matches JAX _pool_masks exactly, fp32) ----
    const float* cor = corners + bp * 6;
    int blo[3], nn[3];
#pragma unroll
    for (int a = 0; a < 3; a++) {
        float ll = __ldg(cor + a)     * 0.25f;
        float ur = __ldg(cor + 3 + a) * 0.25f;
        ll = fminf(fmaxf(ll, 0.0f), 21.0f);
        ur = (ur - ll >= 2.0f) ? ur : (ll + 2.0f);
        ur = fminf(fmaxf(ur, 2.0f), 23.0f);
        int lo = (int)floorf(ll);
        blo[a] = lo;
        nn[a]  = (int)floorf(ur) - lo;   // n in [2, 23]
    }
    // equal-length bins: [lo, lo+m2) and [lo+n/2, lo+n/2+m2), m2 = (n+1)/2
    const int d0   = blo[0], md2 = (nn[0] + 1) >> 1, ddel = (nn[0] >> 1) * 576;
    const int h0   = blo[1], mh2 = (nn[1] + 1) >> 1, hseg = (nn[1] >> 1) * 24;
    const int zlo  = blo[2], mz2 = (nn[2] + 1) >> 1, zhalf = nn[2] >> 1;

    // ---- 2-D lane mapping over (h, z); clamped lanes hit in-bin duplicate
    //      voxels -> no predication anywhere in the main loop ----
    const int W    = nn[2];              // z-union width (2..23)
    const int R    = 32 / W;             // h-rows per load step (1..16)
    const int hrel = lane / W;
    const int zrel = lane - hrel * W;
    const int hcap = mh2 - 1;            // clamp target (inside bin)

    const float* base = fm + ((size_t)(b * 64 + c)) * 13824 + (zlo + zrel);

    float a00 = NEGINF, a01 = NEGINF, a10 = NEGINF, a11 = NEGINF;

    // ---- main loop: this warp takes d index i = half, half+2, ... < md2 ----
    for (int i = half; i < md2; i += 2) {
        const float* pA = base + (d0 + i) * 576;   // kx0 stream
        const float* pC = pA + ddel;               // kx1 stream
        for (int idx0 = 0; idx0 < mh2; idx0 += R) {
            const int ro = (h0 + min(idx0 + hrel, hcap)) * 24;
            const float vA0 = __ldg(pA + ro);
            const float vA1 = __ldg(pA + ro + hseg);
            const float vC0 = __ldg(pC + ro);
            const float vC1 = __ldg(pC + ro + hseg);
            a00 = fmaxf(a00, vA0);
            a01 = fmaxf(a01, vA1);
            a10 = fmaxf(a10, vC0);
            a11 = fmaxf(a11, vC1);
        }
    }

    // ---- per-warp z-bin reductions via redux.sync on monotone keys ----
    const unsigned k00 = f2key(a00), k01 = f2key(a01);
    const unsigned k10 = f2key(a10), k11 = f2key(a11);

#pragma unroll
    for (int kz = 0; kz < 2; kz++) {
        const bool inz = (unsigned)(zrel - (kz ? zhalf : 0)) < (unsigned)mz2;
        unsigned m00 = __reduce_max_sync(0xFFFFFFFFu, inz ? k00 : KEY_NEGINF);
        unsigned m01 = __reduce_max_sync(0xFFFFFFFFu, inz ? k01 : KEY_NEGINF);
        unsigned m10 = __reduce_max_sync(0xFFFFFFFFu, inz ? k10 : KEY_NEGINF);
        unsigned m11 = __reduce_max_sync(0xFFFFFFFFu, inz ? k11 : KEY_NEGINF);
        if (lane == 0) {
            skey[wid][kz + 0] = m00;   // slot = kx*4 + ky*2 + kz
            skey[wid][kz + 2] = m01;
            skey[wid][kz + 4] = m10;
            skey[wid][kz + 6] = m11;
        }
    }
    __syncthreads();

    // ---- combine halves + write: warp 0, one lane per output value ----
    if (wid == 0) {
        const int ocp = lane >> 3;     // channel pair 0..3
        const int k   = lane & 7;      // output slot kx*4+ky*2+kz
        unsigned v = max(skey[ocp * 2 + 0][k], skey[ocp * 2 + 1][k]);
        const int oc = cg * 4 + ocp;
        out[(((size_t)bp * 64 + oc) << 3) + k] = key2f(v);
    }
}

extern "C" void kernel_launch(void* const* d_in, const int* in_sizes, int n_in,
                              void* d_out, int out_size)
{
    const float* fm      = (const float*)d_in[0];
    const float* corners = (const float*)d_in[1];
    float* out           = (float*)d_out;

    // 256 (b,p) x 16 channel-groups = 4096 blocks, 8 warps each
    crop_proposals_kernel<<<4096, 256>>>(fm, corners, out);
}

// round 14
// speedup vs baseline: 1.2882x; 1.1604x over previous
#include <cuda_runtime.h>
#include <math_constants.h>

// CropProposals: 3D ROI 2x2x2 adaptive max-pool.
// fm:      (4, 64, 24, 24, 24) f32   -> d_in[0]
// corners: (4, 64, 2, 3)       f32   -> d_in[1]
// out:     (4, 64, 64, 2, 2, 2) f32
//
// 2-D lane mapping: W = z-union width, lane -> (hrel = lane/W, zrel = lane%W);
// one LDG covers R = 32/W h-rows. Per axis both bins have EQUAL length
// m2=(n+1)/2 at lo and lo+n/2 (shared middle slice, max-idempotent). No
// predication: out-of-range lanes clamp onto in-bin duplicate voxels.
// EACH WARP PROCESSES 2 CHANNELS (c, c+1): channel 2 addressed via +13824
// element (+55296 B) immediate -> 8 independent LDG streams per step, fixed
// per-warp costs amortized 2x. 2 warps per task split d by parity; block =
// 8 warps = 4 channel-slots x 2 halves sharing one (b,p) -> uniform duration.
// z-binning via redux.sync on order-preserving keys; halves combined in smem.

#define NEGINF (-CUDART_INF_F)
#define KEY_NEGINF 0x007FFFFFu   // f2key(-inf)
#define CH_STRIDE 13824          // floats per channel volume

__device__ __forceinline__ unsigned f2key(float f) {
    int i = __float_as_int(f);
    return (unsigned)(i ^ ((i >> 31) | 0x80000000));
}
__device__ __forceinline__ float key2f(unsigned u) {
    int i = (int)(u ^ ((~u >> 31) ? 0xFFFFFFFFu : 0x80000000u));
    return __int_as_float(i);
}

__global__ __launch_bounds__(256) void crop_proposals_kernel(
    const float* __restrict__ fm,
    const float* __restrict__ corners,
    float* __restrict__ out)
{
    __shared__ unsigned skey[8][16];      // [warp][ch*8 + slot]

    const int wid   = threadIdx.x >> 5;   // 0..7
    const int lane  = threadIdx.x & 31;
    const int cslot = wid >> 1;           // 0..3 : channel slot (2 ch each)
    const int half  = wid & 1;            // 0/1  : d-parity split

    const int bp = blockIdx.x >> 3;       // b*64 + p
    const int cg = blockIdx.x & 7;        // channel group (8 channels each)
    const int b  = bp >> 6;
    const int c0 = cg * 8 + cslot * 2;    // first of this warp's 2 channels

    // ---- bin computation (matches JAX _pool_masks exactly, fp32) ----
    const float* cor = corners + bp * 6;
    int blo[3], nn[3];
#pragma unroll
    for (int a = 0; a < 3; a++) {
        float ll = __ldg(cor + a)     * 0.25f;
        float ur = __ldg(cor + 3 + a) * 0.25f;
        ll = fminf(fmaxf(ll, 0.0f), 21.0f);
        ur = (ur - ll >= 2.0f) ? ur : (ll + 2.0f);
        ur = fminf(fmaxf(ur, 2.0f), 23.0f);
        int lo = (int)floorf(ll);
        blo[a] = lo;
        nn[a]  = (int)floorf(ur) - lo;   // n in [2, 23]
    }
    // equal-length bins: [lo, lo+m2) and [lo+n/2, lo+n/2+m2), m2 = (n+1)/2
    const int d0   = blo[0], md2 = (nn[0] + 1) >> 1, ddel = (nn[0] >> 1) * 576;
    const int h0   = blo[1], mh2 = (nn[1] + 1) >> 1, hseg = (nn[1] >> 1) * 24;
    const int zlo  = blo[2], mz2 = (nn[2] + 1) >> 1, zhalf = nn[2] >> 1;

    // ---- 2-D lane mapping over (h, z); clamped lanes hit in-bin duplicates ----
    const int W    = nn[2];              // z-union width (2..23)
    const int R    = 32 / W;             // h-rows per load step (1..16)
    const int hrel = lane / W;
    const int zrel = lane - hrel * W;
    const int hcap = mh2 - 1;            // clamp target (inside bin)

    const float* base = fm + ((size_t)(b * 64 + c0)) * CH_STRIDE + (zlo + zrel);

    float a00 = NEGINF, a01 = NEGINF, a10 = NEGINF, a11 = NEGINF;   // channel c0
    float b00 = NEGINF, b01 = NEGINF, b10 = NEGINF, b11 = NEGINF;   // channel c0+1

    // ---- main loop: this warp takes d index i = half, half+2, ... < md2 ----
    for (int i = half; i < md2; i += 2) {
        const float* pA = base + (d0 + i) * 576;   // kx0 stream, ch0
        const float* pC = pA + ddel;               // kx1 stream, ch0
        for (int idx0 = 0; idx0 < mh2; idx0 += R) {
            const int ro = (h0 + min(idx0 + hrel, hcap)) * 24;
            const float* qA0 = pA + ro;
            const float* qA1 = pA + ro + hseg;
            const float* qC0 = pC + ro;
            const float* qC1 = pC + ro + hseg;
            a00 = fmaxf(a00, __ldg(qA0));
            a01 = fmaxf(a01, __ldg(qA1));
            a10 = fmaxf(a10, __ldg(qC0));
            a11 = fmaxf(a11, __ldg(qC1));
            b00 = fmaxf(b00, __ldg(qA0 + CH_STRIDE));   // imm-offset LDGs
            b01 = fmaxf(b01, __ldg(qA1 + CH_STRIDE));
            b10 = fmaxf(b10, __ldg(qC0 + CH_STRIDE));
            b11 = fmaxf(b11, __ldg(qC1 + CH_STRIDE));
        }
    }

    // ---- per-warp z-bin reductions via redux.sync on monotone keys ----
    const unsigned ka[4] = { f2key(a00), f2key(a01), f2key(a10), f2key(a11) };
    const unsigned kb[4] = { f2key(b00), f2key(b01), f2key(b10), f2key(b11) };

#pragma unroll
    for (int kz = 0; kz < 2; kz++) {
        const bool inz = (unsigned)(zrel - (kz ? zhalf : 0)) < (unsigned)mz2;
#pragma unroll
        for (int q = 0; q < 4; q++) {    // q = kx*2 + ky
            unsigned ma = __reduce_max_sync(0xFFFFFFFFu, inz ? ka[q] : KEY_NEGINF);
            unsigned mb = __reduce_max_sync(0xFFFFFFFFu, inz ? kb[q] : KEY_NEGINF);
            if (lane == 0) {
                skey[wid][q * 2 + kz]     = ma;   // ch0, slot = kx*4+ky*2+kz
                skey[wid][8 + q * 2 + kz] = mb;   // ch1
            }
        }
    }
    __syncthreads();

    // ---- combine halves + write: threads 0..63, one output value each ----
    const int tid = threadIdx.x;
    if (tid < 64) {
        const int ocs = tid >> 4;          // channel slot 0..3
        const int ch  = (tid >> 3) & 1;    // channel within slot
        const int k   = tid & 7;           // output slot kx*4+ky*2+kz
        const int s   = ch * 8 + k;
        unsigned v = max(skey[ocs * 2 + 0][s], skey[ocs * 2 + 1][s]);
        const int oc = cg * 8 + ocs * 2 + ch;
        out[(((size_t)bp * 64 + oc) << 3) + k] = key2f(v);
    }
}

extern "C" void kernel_launch(void* const* d_in, const int* in_sizes, int n_in,
                              void* d_out, int out_size)
{
    const float* fm      = (const float*)d_in[0];
    const float* corners = (const float*)d_in[1];
    float* out           = (float*)d_out;

    // 256 (b,p) x 8 channel-groups = 2048 blocks, 8 warps each
    crop_proposals_kernel<<<2048, 256>>>(fm, corners, out);
}